// round 13
// baseline (speedup 1.0000x reference)
#include <cuda_runtime.h>
#include <cuda_fp16.h>

#define HID   51
#define TT    2048
#define NN    1024
#define CHUNK 64
#define NROWS 208         // 204 layer-1 gate rows + 4 layer-2 gate rows
#define NTH   32          // ONE warp per block, TWO sequences per block

__device__ __forceinline__ float tanhx(float x) {
    float r; asm("tanh.approx.f32 %0, %1;" : "=f"(r) : "f"(x)); return r;
}

__global__ void __launch_bounds__(NTH)
lstm2_kernel(const float* __restrict__ stim,
             const float* __restrict__ Wih1,   // (204,1)
             const float* __restrict__ Whh1,   // (204,51)
             const float* __restrict__ bih1,
             const float* __restrict__ bhh1,
             const float* __restrict__ Wih2,   // (4,51)
             const float* __restrict__ Whh2,   // (4,1)
             const float* __restrict__ bih2,
             const float* __restrict__ bhh2,
             float* __restrict__ out)          // (1024,2048)
{
    __shared__ __align__(16) __half2 hbuf[2][52];   // h pairs (seqA,seqB); [51]=0 pad
    __shared__ __align__(16) unsigned gacc[NROWS];  // packed gate accs (half2 as u32)
    __shared__ __align__(16) float x_sh[2][CHUNK];
    __shared__ __align__(16) float ob_sh[2][CHUNK]; // y(t0+dt-1), 2 seqs

    const int t  = threadIdx.x;
    const int n0 = blockIdx.x * 2;

    // ---- matvec rows r = t + 32*i (i=0..6); r<204: Whh1 row r; 204..207: Wih2 ----
    __half2 wpk[7][26];
#pragma unroll
    for (int i = 0; i < 7; i++)
#pragma unroll
        for (int kk = 0; kk < 26; kk++) wpk[i][kk] = __half2half2(__ushort_as_half(0));
#pragma unroll
    for (int i = 0; i < 7; i++) {
        int r = t + 32 * i;
        if (r < NROWS) {
            const float* src = (r < 204) ? (Whh1 + r * HID) : (Wih2 + (r - 204) * HID);
#pragma unroll
            for (int kk = 0; kk < 26; kk++) {
                float a = src[2*kk];
                float b = (2*kk + 1 < HID) ? src[2*kk + 1] : 0.f;
                wpk[i][kk] = __floats2half2_rn(a, b);
            }
        }
    }

    // ---- owner setup: unit A = t (0..31); unit B = t+32 (t<19) or L2 (t==19) ----
    const bool hasB = (t < 20);
    const bool isl2 = (t == 19);
    float biasA[4], wiA[4], biasB[4], wiB[4];
#pragma unroll
    for (int g = 0; g < 4; g++) {
        const int rowA = g * HID + t;
        biasA[g] = bih1[rowA] + bhh1[rowA];
        wiA[g]   = Wih1[rowA];
        if (t < 19) {
            const int rowB = g * HID + (t + 32);
            biasB[g] = bih1[rowB] + bhh1[rowB];
            wiB[g]   = Wih1[rowB];
        } else if (isl2) {
            biasB[g] = bih2[g] + bhh2[g];
            wiB[g]   = Whh2[g];
        } else { biasB[g] = 0.f; wiB[g] = 0.f; }
    }

    for (int i = t; i < 104; i += NTH) ((unsigned*)hbuf)[i] = 0u;
    float cA0 = 0.f, cA1 = 0.f;        // unit A cell, seq 0/1
    float cB0 = 0.f, cB1 = 0.f;        // unit B (or layer-2) cell, seq 0/1
    float h2a = 0.f, h2b = 0.f;        // layer-2 hidden (thread 19)

    {   // stage chunk 0 stimulus
        int s = t >> 4, q = (t & 15) * 4;
        *(float4*)&x_sh[s][q] = *(const float4*)&stim[(n0 + s) * TT + q];
    }
    __syncwarp();

#pragma unroll 1
    for (int t0 = 0; t0 < TT; t0 += CHUNK) {
#pragma unroll 1
        for (int dt = 0; dt < CHUNK; dt++) {
            const int rd = dt & 1;
            // ---- seq-packed matvec: 364 HFMA2, 7 rows, split accs ------
            __half2 z = __half2half2(__ushort_as_half(0));
            __half2 a1[7] = {z,z,z,z,z,z,z};
            __half2 a2[7] = {z,z,z,z,z,z,z};
            const uint4* h4 = (const uint4*)&hbuf[rd][0];
#pragma unroll
            for (int q = 0; q < 13; q++) {
                uint4 v = h4[q];
                __half2 p0 = *(__half2*)&v.x, p1 = *(__half2*)&v.y;
                __half2 p2 = *(__half2*)&v.z, p3 = *(__half2*)&v.w;
#pragma unroll
                for (int i = 0; i < 7; i++) {
                    a1[i] = __hfma2(__low2half2 (wpk[i][2*q]),   p0, a1[i]);
                    a2[i] = __hfma2(__high2half2(wpk[i][2*q]),   p1, a2[i]);
                    a1[i] = __hfma2(__low2half2 (wpk[i][2*q+1]), p2, a1[i]);
                    a2[i] = __hfma2(__high2half2(wpk[i][2*q+1]), p3, a2[i]);
                }
            }
            // ---- scatter gate accs to unit-major slots -----------------
#pragma unroll
            for (int i = 0; i < 7; i++) {
                int r = t + 32 * i;
                if (r < NROWS) {
                    int slot = (r < 204) ? ((r % HID) * 4 + r / HID) : r;
                    __half2 s2 = __hadd2(a1[i], a2[i]);
                    gacc[slot] = *(unsigned*)&s2;
                }
            }
            __syncwarp();

            // ---- owner phase: finish gates in fp32, update cells -------
            const float xA = x_sh[0][dt];
            const float xB = x_sh[1][dt];
            {   // unit A (all threads)
                uint4 g4 = *(const uint4*)&gacc[t * 4];
                float2 fi = __half22float2(*(__half2*)&g4.x);
                float2 ff = __half22float2(*(__half2*)&g4.y);
                float2 fg = __half22float2(*(__half2*)&g4.z);
                float2 fo = __half22float2(*(__half2*)&g4.w);
                float i0 = fi.x + fmaf(wiA[0], xA, biasA[0]);
                float f0 = ff.x + fmaf(wiA[1], xA, biasA[1]);
                float g0 = fg.x + fmaf(wiA[2], xA, biasA[2]);
                float o0 = fo.x + fmaf(wiA[3], xA, biasA[3]);
                float i1 = fi.y + fmaf(wiA[0], xB, biasA[0]);
                float f1 = ff.y + fmaf(wiA[1], xB, biasA[1]);
                float g1 = fg.y + fmaf(wiA[2], xB, biasA[2]);
                float o1 = fo.y + fmaf(wiA[3], xB, biasA[3]);
                cA0 = fmaf(fmaf(0.5f, tanhx(0.5f * f0), 0.5f), cA0,
                           fmaf(0.5f, tanhx(0.5f * i0), 0.5f) * tanhx(g0));
                cA1 = fmaf(fmaf(0.5f, tanhx(0.5f * f1), 0.5f), cA1,
                           fmaf(0.5f, tanhx(0.5f * i1), 0.5f) * tanhx(g1));
                float hA0 = fmaf(0.5f, tanhx(0.5f * o0), 0.5f) * tanhx(cA0);
                float hA1 = fmaf(0.5f, tanhx(0.5f * o1), 0.5f) * tanhx(cA1);
                hbuf[1 - rd][t] = __floats2half2_rn(hA0, hA1);
            }
            if (hasB) {     // unit B (t<19) or layer-2 (t==19)
                const int base = isl2 ? 204 : (t + 32) * 4;
                uint4 g4 = *(const uint4*)&gacc[base];
                float2 fi = __half22float2(*(__half2*)&g4.x);
                float2 ff = __half22float2(*(__half2*)&g4.y);
                float2 fg = __half22float2(*(__half2*)&g4.z);
                float2 fo = __half22float2(*(__half2*)&g4.w);
                float xb0 = isl2 ? h2a : xA;
                float xb1 = isl2 ? h2b : xB;
                float i0 = fi.x + fmaf(wiB[0], xb0, biasB[0]);
                float f0 = ff.x + fmaf(wiB[1], xb0, biasB[1]);
                float g0 = fg.x + fmaf(wiB[2], xb0, biasB[2]);
                float o0 = fo.x + fmaf(wiB[3], xb0, biasB[3]);
                float i1 = fi.y + fmaf(wiB[0], xb1, biasB[0]);
                float f1 = ff.y + fmaf(wiB[1], xb1, biasB[1]);
                float g1 = fg.y + fmaf(wiB[2], xb1, biasB[2]);
                float o1 = fo.y + fmaf(wiB[3], xb1, biasB[3]);
                if (!isl2) {
                    cB0 = fmaf(fmaf(0.5f, tanhx(0.5f * f0), 0.5f), cB0,
                               fmaf(0.5f, tanhx(0.5f * i0), 0.5f) * tanhx(g0));
                    cB1 = fmaf(fmaf(0.5f, tanhx(0.5f * f1), 0.5f), cB1,
                               fmaf(0.5f, tanhx(0.5f * i1), 0.5f) * tanhx(g1));
                    float hB0 = fmaf(0.5f, tanhx(0.5f * o0), 0.5f) * tanhx(cB0);
                    float hB1 = fmaf(0.5f, tanhx(0.5f * o1), 0.5f) * tanhx(cB1);
                    hbuf[1 - rd][t + 32] = __floats2half2_rn(hB0, hB1);
                } else if ((t0 | dt) != 0) {   // lag-1 layer-2; skip t=0
                    cB0 = fmaf(fmaf(0.5f, tanhx(0.5f * f0), 0.5f), cB0,
                               fmaf(0.5f, tanhx(0.5f * i0), 0.5f) * tanhx(g0));
                    cB1 = fmaf(fmaf(0.5f, tanhx(0.5f * f1), 0.5f), cB1,
                               fmaf(0.5f, tanhx(0.5f * i1), 0.5f) * tanhx(g1));
                    float y0 = fmaf(0.5f, tanhx(0.5f * o0), 0.5f) * tanhx(cB0);
                    float y1 = fmaf(0.5f, tanhx(0.5f * o1), 0.5f) * tanhx(cB1);
                    ob_sh[0][dt] = y0; h2a = y0;
                    ob_sh[1][dt] = y1; h2b = y1;
                }
            }
            __syncwarp();
        }
        // ---- flush outputs (lagged by 1) + stage next chunk ------------
        for (int i = t; i < 2 * CHUNK; i += NTH) {
            int s = i >> 6, col = i & 63;
            int tt = t0 - 1 + col;
            if (tt >= 0) out[(n0 + s) * TT + tt] = ob_sh[s][col];
        }
        if (t0 + CHUNK < TT) {
            int s = t >> 4, q = (t & 15) * 4;
            *(float4*)&x_sh[s][q] =
                *(const float4*)&stim[(n0 + s) * TT + t0 + CHUNK + q];
        }
        __syncwarp();
    }

    // ---- tail: y(2047) from h1(2047) (in hbuf[0]) ----------------------
    {
        __half2 z = __half2half2(__ushort_as_half(0));
        __half2 a1 = z, a2 = z;                // only the i=6 row matters
        const uint4* h4 = (const uint4*)&hbuf[0][0];
#pragma unroll
        for (int q = 0; q < 13; q++) {
            uint4 v = h4[q];
            a1 = __hfma2(__low2half2 (wpk[6][2*q]),   *(__half2*)&v.x, a1);
            a2 = __hfma2(__high2half2(wpk[6][2*q]),   *(__half2*)&v.y, a2);
            a1 = __hfma2(__low2half2 (wpk[6][2*q+1]), *(__half2*)&v.z, a1);
            a2 = __hfma2(__high2half2(wpk[6][2*q+1]), *(__half2*)&v.w, a2);
        }
        int r = t + 192;
        if (r >= 204 && r < NROWS) {
            __half2 s2 = __hadd2(a1, a2);
            gacc[r] = *(unsigned*)&s2;
        }
    }
    __syncwarp();
    if (isl2) {
        uint4 g4 = *(const uint4*)&gacc[204];
        float2 fi = __half22float2(*(__half2*)&g4.x);
        float2 ff = __half22float2(*(__half2*)&g4.y);
        float2 fg = __half22float2(*(__half2*)&g4.z);
        float2 fo = __half22float2(*(__half2*)&g4.w);
        float i0 = fi.x + fmaf(wiB[0], h2a, biasB[0]);
        float f0 = ff.x + fmaf(wiB[1], h2a, biasB[1]);
        float g0 = fg.x + fmaf(wiB[2], h2a, biasB[2]);
        float o0 = fo.x + fmaf(wiB[3], h2a, biasB[3]);
        float i1 = fi.y + fmaf(wiB[0], h2b, biasB[0]);
        float f1 = ff.y + fmaf(wiB[1], h2b, biasB[1]);
        float g1 = fg.y + fmaf(wiB[2], h2b, biasB[2]);
        float o1 = fo.y + fmaf(wiB[3], h2b, biasB[3]);
        cB0 = fmaf(fmaf(0.5f, tanhx(0.5f * f0), 0.5f), cB0,
                   fmaf(0.5f, tanhx(0.5f * i0), 0.5f) * tanhx(g0));
        cB1 = fmaf(fmaf(0.5f, tanhx(0.5f * f1), 0.5f), cB1,
                   fmaf(0.5f, tanhx(0.5f * i1), 0.5f) * tanhx(g1));
        out[(n0 + 0) * TT + (TT - 1)] =
            fmaf(0.5f, tanhx(0.5f * o0), 0.5f) * tanhx(cB0);
        out[(n0 + 1) * TT + (TT - 1)] =
            fmaf(0.5f, tanhx(0.5f * o1), 0.5f) * tanhx(cB1);
    }
}

extern "C" void kernel_launch(void* const* d_in, const int* in_sizes, int n_in,
                              void* d_out, int out_size)
{
    (void)in_sizes; (void)n_in; (void)out_size;
    const float* stim  = (const float*)d_in[0];
    const float* Wih1  = (const float*)d_in[1];
    const float* Whh1  = (const float*)d_in[2];
    const float* bih1  = (const float*)d_in[3];
    const float* bhh1  = (const float*)d_in[4];
    const float* Wih2  = (const float*)d_in[5];
    const float* Whh2  = (const float*)d_in[6];
    const float* bih2  = (const float*)d_in[7];
    const float* bhh2  = (const float*)d_in[8];
    float* out = (float*)d_out;

    lstm2_kernel<<<NN / 2, NTH>>>(stim, Wih1, Whh1, bih1, bhh1,
                                  Wih2, Whh2, bih2, bhh2, out);
}